// round 1
// baseline (speedup 1.0000x reference)
#include <cuda_runtime.h>
#include <cuda_bf16.h>
#include <math.h>

// Shapes (fixed for this problem)
#define BATCH 8
#define CDIM 512
#define HWDIM 4096          // 64*64
#define GROUPS 32
#define CPG 16              // CDIM / GROUPS
#define EPSV 1e-6f

// ---------------- scratch (device globals; no allocation allowed) ----------
__device__ float g_xn[(size_t)BATCH * HWDIM * CDIM];   // normalized, [B,N,C]  64MB
__device__ float g_q [(size_t)BATCH * HWDIM * CDIM];   // 64MB
__device__ float g_k [(size_t)BATCH * HWDIM * CDIM];   // 64MB
__device__ float g_v [(size_t)BATCH * HWDIM * CDIM];   // 64MB
__device__ float g_s [(size_t)BATCH * HWDIM * HWDIM];  // scores, 512MB

// ---------------- GroupNorm: one block per (b, g) --------------------------
__global__ __launch_bounds__(256) void gn_kernel(const float* __restrict__ x,
                                                 const float* __restrict__ gamma,
                                                 const float* __restrict__ beta,
                                                 float* __restrict__ xn) {
    int b = blockIdx.x >> 5;
    int g = blockIdx.x & 31;
    const float* xp = x + ((size_t)b * CDIM + (size_t)g * CPG) * HWDIM;  // 16*4096 contiguous
    const int NEL = CPG * HWDIM;  // 65536

    float s = 0.f, s2 = 0.f;
    for (int i = threadIdx.x; i < NEL; i += 256) {
        float v = xp[i];
        s += v; s2 += v * v;
    }
    __shared__ float rs[256], rs2[256];
    rs[threadIdx.x] = s; rs2[threadIdx.x] = s2;
    __syncthreads();
    for (int st = 128; st > 0; st >>= 1) {
        if (threadIdx.x < st) { rs[threadIdx.x] += rs[threadIdx.x + st];
                                rs2[threadIdx.x] += rs2[threadIdx.x + st]; }
        __syncthreads();
    }
    float mean = rs[0] * (1.f / NEL);
    float var  = rs2[0] * (1.f / NEL) - mean * mean;
    float rstd = rsqrtf(var + EPSV);

    // write transposed into [B, N, C]
    for (int i = threadIdx.x; i < NEL; i += 256) {
        int c  = i & (CPG - 1);
        int hw = i >> 4;
        int cg = g * CPG + c;
        float v = xp[(size_t)c * HWDIM + hw];
        xn[((size_t)b * HWDIM + hw) * CDIM + cg] = (v - mean) * rstd * gamma[cg] + beta[cg];
    }
}

// ---------------- SGEMM NT: C[m,n] = alpha * sum_k A[m,k]*B[n,k] (+bias[n]) -
// 128x128 tile, BK=8, 256 threads, 8x8 per thread. All dims % 128 / %8 == 0.
__global__ __launch_bounds__(256) void gemm_nt(const float* __restrict__ A,
                                               const float* __restrict__ B,
                                               const float* __restrict__ bias,
                                               float* __restrict__ C,
                                               int K, int lda, int ldb, int ldc,
                                               float alpha,
                                               size_t sA, size_t sB, size_t sC) {
    A += (size_t)blockIdx.z * sA;
    B += (size_t)blockIdx.z * sB;
    C += (size_t)blockIdx.z * sC;

    __shared__ float As[8][128];
    __shared__ float Bs[8][128];

    int tid = threadIdx.x;
    int tx = tid & 15, ty = tid >> 4;
    int bm = blockIdx.y * 128, bn = blockIdx.x * 128;

    int lrow = tid >> 1;          // 0..127
    int lcol = (tid & 1) * 4;     // 0 or 4

    float acc[8][8];
    #pragma unroll
    for (int i = 0; i < 8; i++)
        #pragma unroll
        for (int j = 0; j < 8; j++) acc[i][j] = 0.f;

    for (int k0 = 0; k0 < K; k0 += 8) {
        float4 a4 = *(const float4*)(A + (size_t)(bm + lrow) * lda + k0 + lcol);
        float4 b4 = *(const float4*)(B + (size_t)(bn + lrow) * ldb + k0 + lcol);
        __syncthreads();
        As[lcol + 0][lrow] = a4.x; As[lcol + 1][lrow] = a4.y;
        As[lcol + 2][lrow] = a4.z; As[lcol + 3][lrow] = a4.w;
        Bs[lcol + 0][lrow] = b4.x; Bs[lcol + 1][lrow] = b4.y;
        Bs[lcol + 2][lrow] = b4.z; Bs[lcol + 3][lrow] = b4.w;
        __syncthreads();
        #pragma unroll
        for (int k = 0; k < 8; k++) {
            float4 a0 = *(const float4*)&As[k][ty * 8];
            float4 a1 = *(const float4*)&As[k][ty * 8 + 4];
            float4 b0 = *(const float4*)&Bs[k][tx * 8];
            float4 b1 = *(const float4*)&Bs[k][tx * 8 + 4];
            float av[8] = {a0.x,a0.y,a0.z,a0.w,a1.x,a1.y,a1.z,a1.w};
            float bv[8] = {b0.x,b0.y,b0.z,b0.w,b1.x,b1.y,b1.z,b1.w};
            #pragma unroll
            for (int i = 0; i < 8; i++)
                #pragma unroll
                for (int j = 0; j < 8; j++) acc[i][j] += av[i] * bv[j];
        }
    }

    #pragma unroll
    for (int i = 0; i < 8; i++) {
        int m = bm + ty * 8 + i;
        #pragma unroll
        for (int j0 = 0; j0 < 8; j0 += 4) {
            int n = bn + tx * 8 + j0;
            float4 v;
            v.x = acc[i][j0 + 0] * alpha;
            v.y = acc[i][j0 + 1] * alpha;
            v.z = acc[i][j0 + 2] * alpha;
            v.w = acc[i][j0 + 3] * alpha;
            if (bias) {
                v.x += bias[n + 0]; v.y += bias[n + 1];
                v.z += bias[n + 2]; v.w += bias[n + 3];
            }
            *(float4*)(C + (size_t)m * ldc + n) = v;
        }
    }
}

// ---------------- SGEMM NN: C[m,n] = sum_k A[m,k]*B[k,n] ------------------
__global__ __launch_bounds__(256) void gemm_nn(const float* __restrict__ A,
                                               const float* __restrict__ B,
                                               float* __restrict__ C,
                                               int K, int lda, int ldb, int ldc,
                                               size_t sA, size_t sB, size_t sC) {
    A += (size_t)blockIdx.z * sA;
    B += (size_t)blockIdx.z * sB;
    C += (size_t)blockIdx.z * sC;

    __shared__ float As[8][128];
    __shared__ float Bs[8][128];

    int tid = threadIdx.x;
    int tx = tid & 15, ty = tid >> 4;
    int bm = blockIdx.y * 128, bn = blockIdx.x * 128;

    int larow = tid >> 1;
    int lacol = (tid & 1) * 4;
    int lbrow = tid >> 5;          // 0..7
    int lbcol = (tid & 31) * 4;    // 0..124

    float acc[8][8];
    #pragma unroll
    for (int i = 0; i < 8; i++)
        #pragma unroll
        for (int j = 0; j < 8; j++) acc[i][j] = 0.f;

    for (int k0 = 0; k0 < K; k0 += 8) {
        float4 a4 = *(const float4*)(A + (size_t)(bm + larow) * lda + k0 + lacol);
        float4 b4 = *(const float4*)(B + (size_t)(k0 + lbrow) * ldb + bn + lbcol);
        __syncthreads();
        As[lacol + 0][larow] = a4.x; As[lacol + 1][larow] = a4.y;
        As[lacol + 2][larow] = a4.z; As[lacol + 3][larow] = a4.w;
        *(float4*)&Bs[lbrow][lbcol] = b4;
        __syncthreads();
        #pragma unroll
        for (int k = 0; k < 8; k++) {
            float4 a0 = *(const float4*)&As[k][ty * 8];
            float4 a1 = *(const float4*)&As[k][ty * 8 + 4];
            float4 b0 = *(const float4*)&Bs[k][tx * 8];
            float4 b1 = *(const float4*)&Bs[k][tx * 8 + 4];
            float av[8] = {a0.x,a0.y,a0.z,a0.w,a1.x,a1.y,a1.z,a1.w};
            float bv[8] = {b0.x,b0.y,b0.z,b0.w,b1.x,b1.y,b1.z,b1.w};
            #pragma unroll
            for (int i = 0; i < 8; i++)
                #pragma unroll
                for (int j = 0; j < 8; j++) acc[i][j] += av[i] * bv[j];
        }
    }

    #pragma unroll
    for (int i = 0; i < 8; i++) {
        int m = bm + ty * 8 + i;
        #pragma unroll
        for (int j0 = 0; j0 < 8; j0 += 4) {
            int n = bn + tx * 8 + j0;
            float4 v = make_float4(acc[i][j0], acc[i][j0+1], acc[i][j0+2], acc[i][j0+3]);
            *(float4*)(C + (size_t)m * ldc + n) = v;
        }
    }
}

// ---------------- Softmax over rows of S (length 4096), in place ----------
__global__ __launch_bounds__(256) void softmax_kernel(float* __restrict__ S) {
    float* row = S + (size_t)blockIdx.x * HWDIM;
    int tid = threadIdx.x;
    __shared__ float sm[256];

    float m = -1e30f;
    for (int i = tid; i < HWDIM; i += 256) m = fmaxf(m, row[i]);
    sm[tid] = m; __syncthreads();
    for (int st = 128; st > 0; st >>= 1) {
        if (tid < st) sm[tid] = fmaxf(sm[tid], sm[tid + st]);
        __syncthreads();
    }
    m = sm[0];
    __syncthreads();

    float sum = 0.f;
    for (int i = tid; i < HWDIM; i += 256) {
        float e = __expf(row[i] - m);
        row[i] = e;
        sum += e;
    }
    sm[tid] = sum; __syncthreads();
    for (int st = 128; st > 0; st >>= 1) {
        if (tid < st) sm[tid] += sm[tid + st];
        __syncthreads();
    }
    float inv = 1.f / sm[0];
    for (int i = tid; i < HWDIM; i += 256) row[i] *= inv;
}

// ---------------- Residual + transpose back to [B,C,H,W] ------------------
__global__ __launch_bounds__(256) void epilogue_kernel(const float* __restrict__ O,
                                                       const float* __restrict__ x,
                                                       float* __restrict__ out) {
    size_t idx = (size_t)blockIdx.x * 256 + threadIdx.x;   // over B*C*HW
    int hw = (int)(idx & (HWDIM - 1));
    int c  = (int)((idx >> 12) & (CDIM - 1));
    int b  = (int)(idx >> 21);
    out[idx] = x[idx] + O[(((size_t)b << 12) + hw) * CDIM + c];
}

// ---------------- launch ---------------------------------------------------
extern "C" void kernel_launch(void* const* d_in, const int* in_sizes, int n_in,
                              void* d_out, int out_size) {
    const float* x     = (const float*)d_in[0];
    const float* gamma = (const float*)d_in[1];
    const float* beta  = (const float*)d_in[2];
    const float* Wq    = (const float*)d_in[3];
    const float* bq    = (const float*)d_in[4];
    const float* Wk    = (const float*)d_in[5];
    const float* bk    = (const float*)d_in[6];
    const float* Wv    = (const float*)d_in[7];
    const float* bv    = (const float*)d_in[8];
    const float* Wo    = (const float*)d_in[9];
    float* out = (float*)d_out;

    float *xn, *q, *k, *v, *s;
    cudaGetSymbolAddress((void**)&xn, g_xn);
    cudaGetSymbolAddress((void**)&q,  g_q);
    cudaGetSymbolAddress((void**)&k,  g_k);
    cudaGetSymbolAddress((void**)&v,  g_v);
    cudaGetSymbolAddress((void**)&s,  g_s);

    const int M_all = BATCH * HWDIM;            // 32768
    const size_t strQ = (size_t)HWDIM * CDIM;   // per-batch Q/K/V stride
    const size_t strS = (size_t)HWDIM * HWDIM;  // per-batch score stride
    const float inv_sqrt_c = 0.044194173824159216f;  // 1/sqrt(512)

    // 1. GroupNorm -> [B, N, C]
    gn_kernel<<<BATCH * GROUPS, 256>>>(x, gamma, beta, xn);

    // 2. Q/K/V projections: [32768,512] @ W^T + b
    dim3 gproj(CDIM / 128, M_all / 128, 1);
    gemm_nt<<<gproj, 256>>>(xn, Wq, bq, q, CDIM, CDIM, CDIM, CDIM, 1.f, 0, 0, 0);
    gemm_nt<<<gproj, 256>>>(xn, Wk, bk, k, CDIM, CDIM, CDIM, CDIM, 1.f, 0, 0, 0);
    gemm_nt<<<gproj, 256>>>(xn, Wv, bv, v, CDIM, CDIM, CDIM, CDIM, 1.f, 0, 0, 0);

    // 3. S = (Q @ K^T) / sqrt(C), per batch
    dim3 gs(HWDIM / 128, HWDIM / 128, BATCH);
    gemm_nt<<<gs, 256>>>(q, k, nullptr, s, CDIM, CDIM, CDIM, HWDIM,
                         inv_sqrt_c, strQ, strQ, strS);

    // 4. softmax rows
    softmax_kernel<<<M_all, 256>>>(s);

    // 5. A = P @ V  (reuse xn as attention-output buffer)
    dim3 gpv(CDIM / 128, HWDIM / 128, BATCH);
    gemm_nn<<<gpv, 256>>>(s, v, xn, HWDIM, HWDIM, CDIM, CDIM, strS, strQ, strQ);

    // 6. O = A @ Wo^T (reuse q as output buffer)
    gemm_nt<<<gproj, 256>>>(xn, Wo, nullptr, q, CDIM, CDIM, CDIM, CDIM, 1.f, 0, 0, 0);

    // 7. residual + transpose to [B, C, H, W]
    epilogue_kernel<<<(BATCH * CDIM * HWDIM) / 256, 256>>>(q, x, out);
}

// round 3
// speedup vs baseline: 1.5411x; 1.5411x over previous
#include <cuda_runtime.h>
#include <cuda_bf16.h>
#include <math.h>
#include <stdint.h>

// Shapes (fixed for this problem)
#define BATCH 8
#define CDIM 512
#define HWDIM 4096          // 64*64
#define GROUPS 32
#define CPG 16
#define EPSV 1e-6f

// GEMM tiling
#define TM 128
#define TN 128
#define BK 32
#define KPAD 36                         // padded row stride in floats (conflict-free)
#define ASTG (TM * KPAD)                // floats per A stage (4608)
#define STG  (2 * ASTG)                 // floats per stage (A+B)
#define NSTAGE 3
#define SMEM_DYN (NSTAGE * STG * 4)     // 110592 bytes

// ---------------- scratch (device globals) ---------------------------------
__device__ float g_xn[(size_t)BATCH * HWDIM * CDIM];   // 64MB
__device__ float g_q [(size_t)BATCH * HWDIM * CDIM];   // 64MB
__device__ float g_k [(size_t)BATCH * HWDIM * CDIM];   // 64MB
__device__ float g_v [(size_t)BATCH * HWDIM * CDIM];   // 64MB
__device__ float g_vt[(size_t)BATCH * HWDIM * CDIM];   // 64MB, V transposed
__device__ float g_s [(size_t)BATCH * HWDIM * HWDIM];  // 512MB scores

// ---------------- PTX helpers ----------------------------------------------
__device__ __forceinline__ uint32_t smem_u32(const void* p) {
    uint32_t a;
    asm("{ .reg .u64 t; cvta.to.shared.u64 t, %1; cvt.u32.u64 %0, t; }"
        : "=r"(a) : "l"(p));
    return a;
}

__device__ __forceinline__ uint32_t to_tf32(float x) {
    uint32_t u;
    asm("cvt.rna.tf32.f32 %0, %1;" : "=r"(u) : "f"(x));
    return u;
}

__device__ __forceinline__ void mma_tf32(float* c, const uint32_t* a, const uint32_t* b) {
    asm volatile(
        "mma.sync.aligned.m16n8k8.row.col.f32.tf32.tf32.f32 "
        "{%0,%1,%2,%3}, {%4,%5,%6,%7}, {%8,%9}, {%0,%1,%2,%3};"
        : "+f"(c[0]), "+f"(c[1]), "+f"(c[2]), "+f"(c[3])
        : "r"(a[0]), "r"(a[1]), "r"(a[2]), "r"(a[3]), "r"(b[0]), "r"(b[1]));
}

__device__ __forceinline__ void cp16(uint32_t dst, const void* src) {
    asm volatile("cp.async.cg.shared.global [%0], [%1], 16;" :: "r"(dst), "l"(src));
}
#define CP_COMMIT() asm volatile("cp.async.commit_group;" ::: "memory")
#define CP_WAIT1()  asm volatile("cp.async.wait_group 1;" ::: "memory")

// ---------------- tf32 mma.sync GEMM NT: C = alpha * A @ B^T (+ bias) -------
// A: [M,K] lda, B: [N,K] ldb (both K-major), C: [M,N] ldc. 128x128 CTA tile,
// 8 warps, each warp 64x32 (4x4 frags of m16n8k8).
__global__ __launch_bounds__(256) void gemm_tc(const float* __restrict__ A,
                                               const float* __restrict__ B,
                                               const float* __restrict__ bias,
                                               float* __restrict__ C,
                                               int K, int lda, int ldb, int ldc,
                                               float alpha,
                                               size_t sA, size_t sB, size_t sC) {
    extern __shared__ float dsm[];

    A += (size_t)blockIdx.z * sA;
    B += (size_t)blockIdx.z * sB;
    C += (size_t)blockIdx.z * sC;
    int bm = blockIdx.y * TM, bn = blockIdx.x * TN;
    int tid = threadIdx.x, wid = tid >> 5, lane = tid & 31;
    int wm = (wid & 1) * 64;     // warp M offset in tile
    int wn = (wid >> 1) * 32;    // warp N offset in tile

    uint32_t smem_base = smem_u32(dsm);

    // cooperative load map: 2 threads per 128B row (each 4x16B granules)
    int lrow = tid >> 1;          // 0..127
    int lpart = (tid & 1) * 16;   // float offset 0 or 16
    const float* ag = A + (size_t)(bm + lrow) * lda + lpart;
    const float* bg = B + (size_t)(bn + lrow) * ldb + lpart;
    uint32_t sAo = (uint32_t)((lrow * KPAD + lpart) * 4);          // byte offset in A part
    uint32_t sBo = (uint32_t)((ASTG + lrow * KPAD + lpart) * 4);   // byte offset in B part

    const int NC = K / BK;

    // prologue: stages 0,1
    #pragma unroll
    for (int c = 0; c < 2; c++) {
        uint32_t st = smem_base + c * (STG * 4);
        const float* a0 = ag + c * BK;
        const float* b0 = bg + c * BK;
        #pragma unroll
        for (int j = 0; j < 4; j++) cp16(st + sAo + j * 16, a0 + j * 4);
        #pragma unroll
        for (int j = 0; j < 4; j++) cp16(st + sBo + j * 16, b0 + j * 4);
        CP_COMMIT();
    }

    float acc[4][4][4];
    #pragma unroll
    for (int i = 0; i < 4; i++)
        #pragma unroll
        for (int j = 0; j < 4; j++)
            #pragma unroll
            for (int r = 0; r < 4; r++) acc[i][j][r] = 0.f;

    int r4 = lane >> 2, c4 = lane & 3;

    for (int c = 0; c < NC; c++) {
        int buf = c % NSTAGE;
        CP_WAIT1();
        __syncthreads();
        if (c + 2 < NC) {
            uint32_t st = smem_base + ((c + 2) % NSTAGE) * (STG * 4);
            const float* a0 = ag + (c + 2) * BK;
            const float* b0 = bg + (c + 2) * BK;
            #pragma unroll
            for (int j = 0; j < 4; j++) cp16(st + sAo + j * 16, a0 + j * 4);
            #pragma unroll
            for (int j = 0; j < 4; j++) cp16(st + sBo + j * 16, b0 + j * 4);
        }
        CP_COMMIT();

        const float* As = dsm + buf * STG;
        const float* Bs = As + ASTG;

        #pragma unroll
        for (int kf = 0; kf < 4; kf++) {
            uint32_t afr[4][4], bfr[4][2];
            #pragma unroll
            for (int mf = 0; mf < 4; mf++) {
                const float* ap = As + (wm + mf * 16 + r4) * KPAD + kf * 8 + c4;
                afr[mf][0] = to_tf32(ap[0]);
                afr[mf][1] = to_tf32(ap[8 * KPAD]);
                afr[mf][2] = to_tf32(ap[4]);
                afr[mf][3] = to_tf32(ap[8 * KPAD + 4]);
            }
            #pragma unroll
            for (int nf = 0; nf < 4; nf++) {
                const float* bp = Bs + (wn + nf * 8 + r4) * KPAD + kf * 8 + c4;
                bfr[nf][0] = to_tf32(bp[0]);
                bfr[nf][1] = to_tf32(bp[4]);
            }
            #pragma unroll
            for (int mf = 0; mf < 4; mf++)
                #pragma unroll
                for (int nf = 0; nf < 4; nf++)
                    mma_tf32(acc[mf][nf], afr[mf], bfr[nf]);
        }
        __syncthreads();
    }

    // epilogue
    #pragma unroll
    for (int mf = 0; mf < 4; mf++) {
        int m0 = bm + wm + mf * 16 + r4;
        #pragma unroll
        for (int nf = 0; nf < 4; nf++) {
            int n0 = bn + wn + nf * 8 + 2 * c4;
            float bx = 0.f, by = 0.f;
            if (bias) { bx = bias[n0]; by = bias[n0 + 1]; }
            float2 v0 = make_float2(acc[mf][nf][0] * alpha + bx,
                                    acc[mf][nf][1] * alpha + by);
            float2 v1 = make_float2(acc[mf][nf][2] * alpha + bx,
                                    acc[mf][nf][3] * alpha + by);
            *(float2*)(C + (size_t)m0 * ldc + n0) = v0;
            *(float2*)(C + (size_t)(m0 + 8) * ldc + n0) = v1;
        }
    }
}

// ---------------- GroupNorm: one block per (b, g) --------------------------
__global__ __launch_bounds__(256) void gn_kernel(const float* __restrict__ x,
                                                 const float* __restrict__ gamma,
                                                 const float* __restrict__ beta,
                                                 float* __restrict__ xn) {
    int b = blockIdx.x >> 5;
    int g = blockIdx.x & 31;
    const float* xp = x + ((size_t)b * CDIM + (size_t)g * CPG) * HWDIM;
    const int NEL = CPG * HWDIM;

    float s = 0.f, s2 = 0.f;
    for (int i = threadIdx.x; i < NEL; i += 256) {
        float v = xp[i];
        s += v; s2 += v * v;
    }
    __shared__ float rs[256], rs2[256];
    rs[threadIdx.x] = s; rs2[threadIdx.x] = s2;
    __syncthreads();
    for (int st = 128; st > 0; st >>= 1) {
        if (threadIdx.x < st) { rs[threadIdx.x] += rs[threadIdx.x + st];
                                rs2[threadIdx.x] += rs2[threadIdx.x + st]; }
        __syncthreads();
    }
    float mean = rs[0] * (1.f / NEL);
    float var  = rs2[0] * (1.f / NEL) - mean * mean;
    float rstd = rsqrtf(var + EPSV);

    for (int i = threadIdx.x; i < NEL; i += 256) {
        int c  = i & (CPG - 1);
        int hw = i >> 4;
        int cg = g * CPG + c;
        float v = xp[(size_t)c * HWDIM + hw];
        xn[((size_t)b * HWDIM + hw) * CDIM + cg] = (v - mean) * rstd * gamma[cg] + beta[cg];
    }
}

// ---------------- Transpose V: [B, 4096, 512] -> [B, 512, 4096] ------------
__global__ __launch_bounds__(256) void transpose_vt(const float* __restrict__ V,
                                                    float* __restrict__ Vt) {
    __shared__ float t[32][33];
    int b  = blockIdx.z;
    int n0 = blockIdx.x * 32;
    int c0 = blockIdx.y * 32;
    int tx = threadIdx.x & 31, ty = threadIdx.x >> 5;  // 32x8
    const size_t str = (size_t)HWDIM * CDIM;
    #pragma unroll
    for (int i = 0; i < 4; i++)
        t[ty + i * 8][tx] = V[b * str + (size_t)(n0 + ty + i * 8) * CDIM + c0 + tx];
    __syncthreads();
    #pragma unroll
    for (int i = 0; i < 4; i++)
        Vt[b * str + (size_t)(c0 + ty + i * 8) * HWDIM + n0 + tx] = t[tx][ty + i * 8];
}

// ---------------- Softmax over rows of S, single pass via SMEM -------------
__global__ __launch_bounds__(256) void softmax_kernel(float* __restrict__ S) {
    __shared__ float row[HWDIM];
    __shared__ float red[256];
    float* g = S + (size_t)blockIdx.x * HWDIM;
    int tid = threadIdx.x;

    float m = -1e30f;
    #pragma unroll
    for (int i = 0; i < 4; i++) {
        float4 v = *(const float4*)(g + (tid + i * 256) * 4);
        *(float4*)(row + (tid + i * 256) * 4) = v;
        m = fmaxf(m, fmaxf(fmaxf(v.x, v.y), fmaxf(v.z, v.w)));
    }
    red[tid] = m; __syncthreads();
    for (int st = 128; st > 0; st >>= 1) {
        if (tid < st) red[tid] = fmaxf(red[tid], red[tid + st]);
        __syncthreads();
    }
    m = red[0];
    __syncthreads();

    float sum = 0.f;
    #pragma unroll
    for (int i = 0; i < 4; i++) {
        float4 v = *(float4*)(row + (tid + i * 256) * 4);
        v.x = __expf(v.x - m); v.y = __expf(v.y - m);
        v.z = __expf(v.z - m); v.w = __expf(v.w - m);
        *(float4*)(row + (tid + i * 256) * 4) = v;
        sum += v.x + v.y + v.z + v.w;
    }
    red[tid] = sum; __syncthreads();
    for (int st = 128; st > 0; st >>= 1) {
        if (tid < st) red[tid] += red[tid + st];
        __syncthreads();
    }
    float inv = 1.f / red[0];
    #pragma unroll
    for (int i = 0; i < 4; i++) {
        float4 v = *(float4*)(row + (tid + i * 256) * 4);
        v.x *= inv; v.y *= inv; v.z *= inv; v.w *= inv;
        *(float4*)(g + (tid + i * 256) * 4) = v;
    }
}

// ---------------- Residual + transpose back to [B,C,H,W] ------------------
__global__ __launch_bounds__(256) void epilogue_kernel(const float* __restrict__ O,
                                                       const float* __restrict__ x,
                                                       float* __restrict__ out) {
    size_t idx = (size_t)blockIdx.x * 256 + threadIdx.x;
    int hw = (int)(idx & (HWDIM - 1));
    int c  = (int)((idx >> 12) & (CDIM - 1));
    int b  = (int)(idx >> 21);
    out[idx] = x[idx] + O[(((size_t)b << 12) + hw) * CDIM + c];
}

// ---------------- launch ---------------------------------------------------
extern "C" void kernel_launch(void* const* d_in, const int* in_sizes, int n_in,
                              void* d_out, int out_size) {
    const float* x     = (const float*)d_in[0];
    const float* gamma = (const float*)d_in[1];
    const float* beta  = (const float*)d_in[2];
    const float* Wq    = (const float*)d_in[3];
    const float* bq    = (const float*)d_in[4];
    const float* Wk    = (const float*)d_in[5];
    const float* bk    = (const float*)d_in[6];
    const float* Wv    = (const float*)d_in[7];
    const float* bv    = (const float*)d_in[8];
    const float* Wo    = (const float*)d_in[9];
    float* out = (float*)d_out;

    float *xn, *q, *k, *v, *vt, *s;
    cudaGetSymbolAddress((void**)&xn, g_xn);
    cudaGetSymbolAddress((void**)&q,  g_q);
    cudaGetSymbolAddress((void**)&k,  g_k);
    cudaGetSymbolAddress((void**)&v,  g_v);
    cudaGetSymbolAddress((void**)&vt, g_vt);
    cudaGetSymbolAddress((void**)&s,  g_s);

    static bool attr_set = false;
    if (!attr_set) {
        cudaFuncSetAttribute(gemm_tc, cudaFuncAttributeMaxDynamicSharedMemorySize, SMEM_DYN);
        attr_set = true;
    }

    const int M_all = BATCH * HWDIM;             // 32768
    const size_t strQ = (size_t)HWDIM * CDIM;
    const size_t strS = (size_t)HWDIM * HWDIM;
    const float inv_sqrt_c = 0.044194173824159216f;  // 1/sqrt(512)

    // 1. GroupNorm -> [B, N, C]
    gn_kernel<<<BATCH * GROUPS, 256>>>(x, gamma, beta, xn);

    // 2. Q/K/V projections
    dim3 gproj(CDIM / TN, M_all / TM, 1);
    gemm_tc<<<gproj, 256, SMEM_DYN>>>(xn, Wq, bq, q, CDIM, CDIM, CDIM, CDIM, 1.f, 0, 0, 0);
    gemm_tc<<<gproj, 256, SMEM_DYN>>>(xn, Wk, bk, k, CDIM, CDIM, CDIM, CDIM, 1.f, 0, 0, 0);
    gemm_tc<<<gproj, 256, SMEM_DYN>>>(xn, Wv, bv, v, CDIM, CDIM, CDIM, CDIM, 1.f, 0, 0, 0);

    // 3. V^T for the P@V NT GEMM
    dim3 gtr(HWDIM / 32, CDIM / 32, BATCH);
    transpose_vt<<<gtr, 256>>>(v, vt);

    // 4. S = (Q @ K^T) / sqrt(C)
    dim3 gs(HWDIM / TN, HWDIM / TM, BATCH);
    gemm_tc<<<gs, 256, SMEM_DYN>>>(q, k, nullptr, s, CDIM, CDIM, CDIM, HWDIM,
                                   inv_sqrt_c, strQ, strQ, strS);

    // 5. softmax rows (in place)
    softmax_kernel<<<M_all, 256>>>(s);

    // 6. A = P @ V = P @ Vt^T  -> xn (reused)
    dim3 gpv(CDIM / TN, HWDIM / TM, BATCH);
    gemm_tc<<<gpv, 256, SMEM_DYN>>>(s, vt, nullptr, xn, HWDIM, HWDIM, HWDIM, CDIM,
                                    1.f, strS, strQ, strQ);

    // 7. O = A @ Wo^T -> q (reused)
    gemm_tc<<<gproj, 256, SMEM_DYN>>>(xn, Wo, nullptr, q, CDIM, CDIM, CDIM, CDIM, 1.f, 0, 0, 0);

    // 8. residual + transpose to [B, C, H, W]
    epilogue_kernel<<<(size_t)(BATCH * CDIM) * HWDIM / 256, 256>>>(q, x, out);
}

// round 4
// speedup vs baseline: 5.5879x; 3.6258x over previous
#include <cuda_runtime.h>
#include <cuda_bf16.h>
#include <math.h>
#include <stdint.h>

// Shapes (fixed)
#define BATCH 8
#define CDIM 512
#define HWDIM 4096
#define CPG 16
#define EPSV 1e-6f

// GEMM tiling: 128x128 CTA tile, BK=64 bf16 (128B rows), 3-stage cp.async
#define TM 128
#define TN 128
#define BK 64
#define TILE_BYTES (TM * 128)           // 16KB per operand stage
#define STG_BYTES (2 * TILE_BYTES)      // 32KB
#define NSTAGE 3
#define SMEM_DYN (NSTAGE * STG_BYTES)   // 96KB

typedef __nv_bfloat16 bf16;
typedef __nv_bfloat162 bf162;

// ---------------- scratch (device globals) ---------------------------------
__device__ bf16  g_xnb [(size_t)BATCH * HWDIM * CDIM];   // 32MB  GN out [B,N,C]
__device__ bf16  g_qb  [(size_t)BATCH * HWDIM * CDIM];   // 32MB
__device__ bf16  g_kb  [(size_t)BATCH * HWDIM * CDIM];   // 32MB
__device__ bf16  g_vb  [(size_t)BATCH * HWDIM * CDIM];   // 32MB
__device__ bf16  g_vtb [(size_t)BATCH * HWDIM * CDIM];   // 32MB  V^T [B,C,N]
__device__ bf16  g_pb  [(size_t)BATCH * HWDIM * HWDIM];  // 256MB softmax(P) bf16
__device__ bf16  g_attnb[(size_t)BATCH * HWDIM * CDIM];  // 32MB  P@V out
__device__ bf16  g_wb  [4 * CDIM * CDIM];                // 2MB   bf16 weights
__device__ float g_s   [(size_t)BATCH * HWDIM * HWDIM];  // 512MB scores f32
__device__ float g_o   [(size_t)BATCH * HWDIM * CDIM];   // 64MB  O proj out f32

// ---------------- PTX helpers ----------------------------------------------
__device__ __forceinline__ uint32_t smem_u32(const void* p) {
    uint32_t a;
    asm("{ .reg .u64 t; cvta.to.shared.u64 t, %1; cvt.u32.u64 %0, t; }"
        : "=r"(a) : "l"(p));
    return a;
}

__device__ __forceinline__ void ldsm4(uint32_t* r, uint32_t addr) {
    asm volatile("ldmatrix.sync.aligned.m8n8.x4.shared.b16 {%0,%1,%2,%3}, [%4];"
                 : "=r"(r[0]), "=r"(r[1]), "=r"(r[2]), "=r"(r[3]) : "r"(addr));
}

__device__ __forceinline__ void mma_bf16(float* c, const uint32_t* a,
                                         uint32_t b0, uint32_t b1) {
    asm volatile(
        "mma.sync.aligned.m16n8k16.row.col.f32.bf16.bf16.f32 "
        "{%0,%1,%2,%3}, {%4,%5,%6,%7}, {%8,%9}, {%0,%1,%2,%3};"
        : "+f"(c[0]), "+f"(c[1]), "+f"(c[2]), "+f"(c[3])
        : "r"(a[0]), "r"(a[1]), "r"(a[2]), "r"(a[3]), "r"(b0), "r"(b1));
}

__device__ __forceinline__ void cp16(uint32_t dst, const void* src) {
    asm volatile("cp.async.cg.shared.global [%0], [%1], 16;" :: "r"(dst), "l"(src));
}
#define CP_COMMIT() asm volatile("cp.async.commit_group;" ::: "memory")
#define CP_WAIT1()  asm volatile("cp.async.wait_group 1;" ::: "memory")

// ---------------- bf16 GEMM NT: C = alpha * A @ B^T (+ bias) ----------------
// A: [M,K] lda, B: [N,K] ldb bf16 K-major. C: f32 or bf16 per c_bf16 flag.
__global__ __launch_bounds__(256) void gemm_bf16(const bf16* __restrict__ A,
                                                 const bf16* __restrict__ B,
                                                 const float* __restrict__ bias,
                                                 void* __restrict__ Cv,
                                                 int K, int lda, int ldb, int ldc,
                                                 float alpha, int c_bf16,
                                                 size_t sA, size_t sB, size_t sC) {
    extern __shared__ char dsm[];
    uint32_t smem_base = smem_u32(dsm);

    A += (size_t)blockIdx.z * sA;
    B += (size_t)blockIdx.z * sB;
    int bm = blockIdx.y * TM, bn = blockIdx.x * TN;
    int tid = threadIdx.x, wid = tid >> 5, lane = tid & 31;
    int wm = (wid & 1) * 64, wn = (wid >> 1) * 32;

    // cooperative load: 2 threads per 128B row; XOR swizzle granule ^= row&7
    int lrow = tid >> 1;
    int g0 = (tid & 1) * 4;
    const bf16* ag = A + (size_t)(bm + lrow) * lda + g0 * 8;
    const bf16* bg = B + (size_t)(bn + lrow) * ldb + g0 * 8;
    int rx = lrow & 7;
    uint32_t sAoff[4], sBoff[4];
    #pragma unroll
    for (int j = 0; j < 4; j++) {
        uint32_t o = (uint32_t)lrow * 128 + (uint32_t)(((g0 + j) ^ rx) << 4);
        sAoff[j] = o;
        sBoff[j] = TILE_BYTES + o;
    }

    // ldmatrix lane addressing (tile-relative byte offsets)
    int arl = (lane & 7) + ((lane >> 3) & 1) * 8;   // row within 16-row frag
    int ahi = lane >> 4;                            // k 16B-half
    uint32_t a_rowoff[4]; int a_rx[4];
    #pragma unroll
    for (int mf = 0; mf < 4; mf++) {
        int row = wm + mf * 16 + arl;
        a_rowoff[mf] = (uint32_t)row * 128;
        a_rx[mf] = row & 7;
    }
    int brl = (lane & 7) + ((lane >> 4) & 1) * 8;
    int bhi = (lane >> 3) & 1;
    uint32_t b_rowoff[2]; int b_rx[2];
    #pragma unroll
    for (int ng = 0; ng < 2; ng++) {
        int row = wn + ng * 16 + brl;
        b_rowoff[ng] = TILE_BYTES + (uint32_t)row * 128;
        b_rx[ng] = row & 7;
    }

    const int NC = K / BK;

    // prologue: stages 0,1
    #pragma unroll
    for (int c = 0; c < 2; c++) {
        uint32_t st = smem_base + c * STG_BYTES;
        const bf16* a0 = ag + c * BK;
        const bf16* b0 = bg + c * BK;
        #pragma unroll
        for (int j = 0; j < 4; j++) cp16(st + sAoff[j], a0 + j * 8);
        #pragma unroll
        for (int j = 0; j < 4; j++) cp16(st + sBoff[j], b0 + j * 8);
        CP_COMMIT();
    }

    float acc[4][4][4];
    #pragma unroll
    for (int i = 0; i < 4; i++)
        #pragma unroll
        for (int j = 0; j < 4; j++)
            #pragma unroll
            for (int r = 0; r < 4; r++) acc[i][j][r] = 0.f;

    for (int c = 0; c < NC; c++) {
        int buf = c % NSTAGE;
        CP_WAIT1();
        __syncthreads();
        if (c + 2 < NC) {
            uint32_t st = smem_base + ((c + 2) % NSTAGE) * STG_BYTES;
            const bf16* a0 = ag + (c + 2) * BK;
            const bf16* b0 = bg + (c + 2) * BK;
            #pragma unroll
            for (int j = 0; j < 4; j++) cp16(st + sAoff[j], a0 + j * 8);
            #pragma unroll
            for (int j = 0; j < 4; j++) cp16(st + sBoff[j], b0 + j * 8);
        }
        CP_COMMIT();

        uint32_t base = smem_base + buf * STG_BYTES;
        #pragma unroll
        for (int kf = 0; kf < 4; kf++) {
            uint32_t a[4][4], b[2][4];
            #pragma unroll
            for (int mf = 0; mf < 4; mf++)
                ldsm4(a[mf], base + a_rowoff[mf] +
                      (uint32_t)(((((kf << 1) | ahi)) ^ a_rx[mf]) << 4));
            #pragma unroll
            for (int ng = 0; ng < 2; ng++)
                ldsm4(b[ng], base + b_rowoff[ng] +
                      (uint32_t)(((((kf << 1) | bhi)) ^ b_rx[ng]) << 4));
            #pragma unroll
            for (int mf = 0; mf < 4; mf++)
                #pragma unroll
                for (int ng = 0; ng < 2; ng++) {
                    mma_bf16(acc[mf][ng * 2 + 0], a[mf], b[ng][0], b[ng][1]);
                    mma_bf16(acc[mf][ng * 2 + 1], a[mf], b[ng][2], b[ng][3]);
                }
        }
        __syncthreads();
    }

    // epilogue
    int r4 = lane >> 2, c2 = (lane & 3) * 2;
    #pragma unroll
    for (int mf = 0; mf < 4; mf++) {
        int m0 = bm + wm + mf * 16 + r4;
        #pragma unroll
        for (int nf = 0; nf < 4; nf++) {
            int n0 = bn + wn + (nf >> 1) * 16 + (nf & 1) * 8 + c2;
            float bx = 0.f, by = 0.f;
            if (bias) { bx = bias[n0]; by = bias[n0 + 1]; }
            float* ac = acc[mf][nf];
            float x0 = ac[0] * alpha + bx, y0 = ac[1] * alpha + by;
            float x1 = ac[2] * alpha + bx, y1 = ac[3] * alpha + by;
            if (c_bf16) {
                bf16* C = (bf16*)Cv + blockIdx.z * sC;
                bf162 h0 = __floats2bfloat162_rn(x0, y0);
                bf162 h1 = __floats2bfloat162_rn(x1, y1);
                *(bf162*)(C + (size_t)m0 * ldc + n0) = h0;
                *(bf162*)(C + (size_t)(m0 + 8) * ldc + n0) = h1;
            } else {
                float* C = (float*)Cv + blockIdx.z * sC;
                *(float2*)(C + (size_t)m0 * ldc + n0) = make_float2(x0, y0);
                *(float2*)(C + (size_t)(m0 + 8) * ldc + n0) = make_float2(x1, y1);
            }
        }
    }
}

// ---------------- weight f32 -> bf16 ---------------------------------------
__global__ __launch_bounds__(256) void convert_w(const float* __restrict__ W,
                                                 bf16* __restrict__ out) {
    int i = blockIdx.x * 256 + threadIdx.x;
    out[i] = __float2bfloat16(W[i]);
}

// ---------------- GroupNorm -> bf16 [B,N,C] --------------------------------
__global__ __launch_bounds__(256) void gn_kernel(const float* __restrict__ x,
                                                 const float* __restrict__ gamma,
                                                 const float* __restrict__ beta,
                                                 bf16* __restrict__ xn) {
    int b = blockIdx.x >> 5;
    int g = blockIdx.x & 31;
    const float* xp = x + ((size_t)b * CDIM + (size_t)g * CPG) * HWDIM;
    const int NEL = CPG * HWDIM;

    float s = 0.f, s2 = 0.f;
    for (int i = threadIdx.x; i < NEL; i += 256) {
        float v = xp[i];
        s += v; s2 += v * v;
    }
    __shared__ float rs[256], rs2[256];
    rs[threadIdx.x] = s; rs2[threadIdx.x] = s2;
    __syncthreads();
    for (int st = 128; st > 0; st >>= 1) {
        if (threadIdx.x < st) { rs[threadIdx.x] += rs[threadIdx.x + st];
                                rs2[threadIdx.x] += rs2[threadIdx.x + st]; }
        __syncthreads();
    }
    float mean = rs[0] * (1.f / NEL);
    float var  = rs2[0] * (1.f / NEL) - mean * mean;
    float rstd = rsqrtf(var + EPSV);

    for (int i = threadIdx.x; i < NEL; i += 256) {
        int c  = i & (CPG - 1);
        int hw = i >> 4;
        int cg = g * CPG + c;
        float v = xp[(size_t)c * HWDIM + hw];
        xn[((size_t)b * HWDIM + hw) * CDIM + cg] =
            __float2bfloat16((v - mean) * rstd * gamma[cg] + beta[cg]);
    }
}

// ---------------- Transpose V (bf16): [B,N,C] -> [B,C,N] --------------------
__global__ __launch_bounds__(256) void transpose_vt(const bf16* __restrict__ V,
                                                    bf16* __restrict__ Vt) {
    __shared__ bf16 t[32][34];
    int b  = blockIdx.z;
    int n0 = blockIdx.x * 32;
    int c0 = blockIdx.y * 32;
    int tx = threadIdx.x & 31, ty = threadIdx.x >> 5;  // 32x8
    const size_t str = (size_t)HWDIM * CDIM;
    #pragma unroll
    for (int i = 0; i < 4; i++)
        t[ty + i * 8][tx] = V[b * str + (size_t)(n0 + ty + i * 8) * CDIM + c0 + tx];
    __syncthreads();
    #pragma unroll
    for (int i = 0; i < 4; i++)
        Vt[b * str + (size_t)(c0 + ty + i * 8) * HWDIM + n0 + tx] = t[tx][ty + i * 8];
}

// ---------------- Softmax: f32 S row -> bf16 P row --------------------------
__global__ __launch_bounds__(256) void softmax_kernel(const float* __restrict__ S,
                                                      bf16* __restrict__ P) {
    __shared__ float row[HWDIM];
    __shared__ float red[256];
    const float* g = S + (size_t)blockIdx.x * HWDIM;
    bf16* p = P + (size_t)blockIdx.x * HWDIM;
    int tid = threadIdx.x;

    float m = -1e30f;
    #pragma unroll
    for (int i = 0; i < 4; i++) {
        float4 v = *(const float4*)(g + (tid + i * 256) * 4);
        *(float4*)(row + (tid + i * 256) * 4) = v;
        m = fmaxf(m, fmaxf(fmaxf(v.x, v.y), fmaxf(v.z, v.w)));
    }
    red[tid] = m; __syncthreads();
    for (int st = 128; st > 0; st >>= 1) {
        if (tid < st) red[tid] = fmaxf(red[tid], red[tid + st]);
        __syncthreads();
    }
    m = red[0];
    __syncthreads();

    float sum = 0.f;
    #pragma unroll
    for (int i = 0; i < 4; i++) {
        float4 v = *(float4*)(row + (tid + i * 256) * 4);
        v.x = __expf(v.x - m); v.y = __expf(v.y - m);
        v.z = __expf(v.z - m); v.w = __expf(v.w - m);
        *(float4*)(row + (tid + i * 256) * 4) = v;
        sum += v.x + v.y + v.z + v.w;
    }
    red[tid] = sum; __syncthreads();
    for (int st = 128; st > 0; st >>= 1) {
        if (tid < st) red[tid] += red[tid + st];
        __syncthreads();
    }
    float inv = 1.f / red[0];
    #pragma unroll
    for (int i = 0; i < 4; i++) {
        int i4 = (tid + i * 256) * 4;
        float4 v = *(float4*)(row + i4);
        bf162 h0 = __floats2bfloat162_rn(v.x * inv, v.y * inv);
        bf162 h1 = __floats2bfloat162_rn(v.z * inv, v.w * inv);
        uint2 pk;
        pk.x = *(uint32_t*)&h0;
        pk.y = *(uint32_t*)&h1;
        *(uint2*)(p + i4) = pk;
    }
}

// ---------------- Residual + transpose back to [B,C,H,W] -------------------
__global__ __launch_bounds__(256) void epilogue_kernel(const float* __restrict__ O,
                                                       const float* __restrict__ x,
                                                       float* __restrict__ out) {
    size_t idx = (size_t)blockIdx.x * 256 + threadIdx.x;
    int hw = (int)(idx & (HWDIM - 1));
    int c  = (int)((idx >> 12) & (CDIM - 1));
    int b  = (int)(idx >> 21);
    out[idx] = x[idx] + O[(((size_t)b << 12) + hw) * CDIM + c];
}

// ---------------- launch ----------------------------------------------------
extern "C" void kernel_launch(void* const* d_in, const int* in_sizes, int n_in,
                              void* d_out, int out_size) {
    const float* x     = (const float*)d_in[0];
    const float* gamma = (const float*)d_in[1];
    const float* beta  = (const float*)d_in[2];
    const float* Wq    = (const float*)d_in[3];
    const float* bq    = (const float*)d_in[4];
    const float* Wk    = (const float*)d_in[5];
    const float* bk    = (const float*)d_in[6];
    const float* Wv    = (const float*)d_in[7];
    const float* bv    = (const float*)d_in[8];
    const float* Wo    = (const float*)d_in[9];
    float* out = (float*)d_out;

    bf16 *xnb, *qb, *kb, *vb, *vtb, *pb, *attnb, *wb;
    float *s, *o;
    cudaGetSymbolAddress((void**)&xnb,   g_xnb);
    cudaGetSymbolAddress((void**)&qb,    g_qb);
    cudaGetSymbolAddress((void**)&kb,    g_kb);
    cudaGetSymbolAddress((void**)&vb,    g_vb);
    cudaGetSymbolAddress((void**)&vtb,   g_vtb);
    cudaGetSymbolAddress((void**)&pb,    g_pb);
    cudaGetSymbolAddress((void**)&attnb, g_attnb);
    cudaGetSymbolAddress((void**)&wb,    g_wb);
    cudaGetSymbolAddress((void**)&s,     g_s);
    cudaGetSymbolAddress((void**)&o,     g_o);

    static bool attr_set = false;
    if (!attr_set) {
        cudaFuncSetAttribute(gemm_bf16, cudaFuncAttributeMaxDynamicSharedMemorySize, SMEM_DYN);
        attr_set = true;
    }

    const int M_all = BATCH * HWDIM;              // 32768
    const size_t strQ = (size_t)HWDIM * CDIM;
    const size_t strS = (size_t)HWDIM * HWDIM;
    const int WN = CDIM * CDIM;                   // 262144
    const float inv_sqrt_c = 0.044194173824159216f;

    bf16* wqb = wb;
    bf16* wkb = wb + WN;
    bf16* wvb = wb + 2 * WN;
    bf16* wob = wb + 3 * WN;

    // 0. weights -> bf16
    convert_w<<<WN / 256, 256>>>(Wq, wqb);
    convert_w<<<WN / 256, 256>>>(Wk, wkb);
    convert_w<<<WN / 256, 256>>>(Wv, wvb);
    convert_w<<<WN / 256, 256>>>(Wo, wob);

    // 1. GroupNorm -> bf16 [B,N,C]
    gn_kernel<<<BATCH * 32, 256>>>(x, gamma, beta, xnb);

    // 2. Q/K/V projections (bf16 out)
    dim3 gproj(CDIM / TN, M_all / TM, 1);
    gemm_bf16<<<gproj, 256, SMEM_DYN>>>(xnb, wqb, bq, qb, CDIM, CDIM, CDIM, CDIM, 1.f, 1, 0, 0, 0);
    gemm_bf16<<<gproj, 256, SMEM_DYN>>>(xnb, wkb, bk, kb, CDIM, CDIM, CDIM, CDIM, 1.f, 1, 0, 0, 0);
    gemm_bf16<<<gproj, 256, SMEM_DYN>>>(xnb, wvb, bv, vb, CDIM, CDIM, CDIM, CDIM, 1.f, 1, 0, 0, 0);

    // 3. V^T
    dim3 gtr(HWDIM / 32, CDIM / 32, BATCH);
    transpose_vt<<<gtr, 256>>>(vb, vtb);

    // 4. S = (Q @ K^T) / sqrt(C)  (f32 out)
    dim3 gs(HWDIM / TN, HWDIM / TM, BATCH);
    gemm_bf16<<<gs, 256, SMEM_DYN>>>(qb, kb, nullptr, s, CDIM, CDIM, CDIM, HWDIM,
                                     inv_sqrt_c, 0, strQ, strQ, strS);

    // 5. softmax -> bf16 P
    softmax_kernel<<<M_all, 256>>>(s, pb);

    // 6. A = P @ Vt^T  (bf16 out)
    dim3 gpv(CDIM / TN, HWDIM / TM, BATCH);
    gemm_bf16<<<gpv, 256, SMEM_DYN>>>(pb, vtb, nullptr, attnb, HWDIM, HWDIM, HWDIM, CDIM,
                                      1.f, 1, strS, strQ, strQ);

    // 7. O = A @ Wo^T  (f32 out)
    gemm_bf16<<<gproj, 256, SMEM_DYN>>>(attnb, wob, nullptr, o, CDIM, CDIM, CDIM, CDIM,
                                        1.f, 0, 0, 0, 0);

    // 8. residual + transpose to [B,C,H,W]
    epilogue_kernel<<<(size_t)(BATCH * CDIM) * HWDIM / 256, 256>>>(o, x, out);
}

// round 5
// speedup vs baseline: 5.9112x; 1.0579x over previous
#include <cuda_runtime.h>
#include <cuda_bf16.h>
#include <math.h>
#include <stdint.h>

// Shapes (fixed)
#define BATCH 8
#define CDIM 512
#define HWDIM 4096
#define CPG 16
#define EPSV 1e-6f

// GEMM tiling: 128x128 CTA tile, BK=64 bf16 (128B rows), 3-stage cp.async
#define TM 128
#define TN 128
#define BK 64
#define TILE_BYTES (TM * 128)           // 16KB per operand stage
#define STG_BYTES (2 * TILE_BYTES)      // 32KB
#define NSTAGE 3
#define SMEM_DYN (NSTAGE * STG_BYTES)   // 96KB

typedef __nv_bfloat16 bf16;
typedef __nv_bfloat162 bf162;

// ---------------- scratch (device globals) ---------------------------------
__device__ bf16  g_xnb [(size_t)BATCH * HWDIM * CDIM];   // 32MB  GN out [B,N,C]
__device__ bf16  g_qb  [(size_t)BATCH * HWDIM * CDIM];   // 32MB
__device__ bf16  g_kb  [(size_t)BATCH * HWDIM * CDIM];   // 32MB
__device__ bf16  g_vb  [(size_t)BATCH * HWDIM * CDIM];   // 32MB
__device__ bf16  g_vtb [(size_t)BATCH * HWDIM * CDIM];   // 32MB  V^T [B,C,N]
__device__ bf16  g_pb  [(size_t)BATCH * HWDIM * HWDIM];  // 256MB softmax(P) bf16
__device__ bf16  g_attnb[(size_t)BATCH * HWDIM * CDIM];  // 32MB  P@V out
__device__ bf16  g_wb  [4 * CDIM * CDIM];                // 2MB   bf16 weights
__device__ float g_s   [(size_t)BATCH * HWDIM * HWDIM];  // 512MB scores f32

// ---------------- PTX helpers ----------------------------------------------
__device__ __forceinline__ uint32_t smem_u32(const void* p) {
    uint32_t a;
    asm("{ .reg .u64 t; cvta.to.shared.u64 t, %1; cvt.u32.u64 %0, t; }"
        : "=r"(a) : "l"(p));
    return a;
}

__device__ __forceinline__ void ldsm4(uint32_t* r, uint32_t addr) {
    asm volatile("ldmatrix.sync.aligned.m8n8.x4.shared.b16 {%0,%1,%2,%3}, [%4];"
                 : "=r"(r[0]), "=r"(r[1]), "=r"(r[2]), "=r"(r[3]) : "r"(addr));
}

__device__ __forceinline__ void mma_bf16(float* c, const uint32_t* a,
                                         uint32_t b0, uint32_t b1) {
    asm volatile(
        "mma.sync.aligned.m16n8k16.row.col.f32.bf16.bf16.f32 "
        "{%0,%1,%2,%3}, {%4,%5,%6,%7}, {%8,%9}, {%0,%1,%2,%3};"
        : "+f"(c[0]), "+f"(c[1]), "+f"(c[2]), "+f"(c[3])
        : "r"(a[0]), "r"(a[1]), "r"(a[2]), "r"(a[3]), "r"(b0), "r"(b1));
}

__device__ __forceinline__ void cp16(uint32_t dst, const void* src) {
    asm volatile("cp.async.cg.shared.global [%0], [%1], 16;" :: "r"(dst), "l"(src));
}
#define CP_COMMIT() asm volatile("cp.async.commit_group;" ::: "memory")
#define CP_WAIT1()  asm volatile("cp.async.wait_group 1;" ::: "memory")

// ---------------- bf16 GEMM NT: C = alpha * A @ B^T (+ bias) ----------------
// A: [M,K] lda, B: [N,K] ldb bf16 K-major.
// mode 0: f32 C row-major   mode 1: bf16 C row-major
// mode 2: fused residual + transpose: out[(m>>12)*512 + n][m&4095] = acc + x[...]
__global__ __launch_bounds__(256, 2) void gemm_bf16(const bf16* __restrict__ A,
                                                    const bf16* __restrict__ B,
                                                    const float* __restrict__ bias,
                                                    void* __restrict__ Cv,
                                                    const float* __restrict__ xres,
                                                    int K, int lda, int ldb, int ldc,
                                                    float alpha, int mode,
                                                    size_t sA, size_t sB, size_t sC) {
    extern __shared__ char dsm[];
    uint32_t smem_base = smem_u32(dsm);

    A += (size_t)blockIdx.z * sA;
    B += (size_t)blockIdx.z * sB;
    int bm = blockIdx.y * TM, bn = blockIdx.x * TN;
    int tid = threadIdx.x, wid = tid >> 5, lane = tid & 31;
    int wm = (wid & 1) * 64, wn = (wid >> 1) * 32;

    // cooperative load: 2 threads per 128B row; XOR swizzle granule ^= row&7
    int lrow = tid >> 1;
    int g0 = (tid & 1) * 4;
    const bf16* ag = A + (size_t)(bm + lrow) * lda + g0 * 8;
    const bf16* bg = B + (size_t)(bn + lrow) * ldb + g0 * 8;
    int rx = lrow & 7;
    uint32_t sAoff[4], sBoff[4];
    #pragma unroll
    for (int j = 0; j < 4; j++) {
        uint32_t o = (uint32_t)lrow * 128 + (uint32_t)(((g0 + j) ^ rx) << 4);
        sAoff[j] = o;
        sBoff[j] = TILE_BYTES + o;
    }

    // ldmatrix lane addressing (tile-relative byte offsets)
    int arl = (lane & 7) + ((lane >> 3) & 1) * 8;
    int ahi = lane >> 4;
    uint32_t a_rowoff[4]; int a_rx[4];
    #pragma unroll
    for (int mf = 0; mf < 4; mf++) {
        int row = wm + mf * 16 + arl;
        a_rowoff[mf] = (uint32_t)row * 128;
        a_rx[mf] = row & 7;
    }
    int brl = (lane & 7) + ((lane >> 4) & 1) * 8;
    int bhi = (lane >> 3) & 1;
    uint32_t b_rowoff[2]; int b_rx[2];
    #pragma unroll
    for (int ng = 0; ng < 2; ng++) {
        int row = wn + ng * 16 + brl;
        b_rowoff[ng] = TILE_BYTES + (uint32_t)row * 128;
        b_rx[ng] = row & 7;
    }

    const int NC = K / BK;

    // prologue: stages 0,1
    #pragma unroll
    for (int c = 0; c < 2; c++) {
        uint32_t st = smem_base + c * STG_BYTES;
        const bf16* a0 = ag + c * BK;
        const bf16* b0 = bg + c * BK;
        #pragma unroll
        for (int j = 0; j < 4; j++) cp16(st + sAoff[j], a0 + j * 8);
        #pragma unroll
        for (int j = 0; j < 4; j++) cp16(st + sBoff[j], b0 + j * 8);
        CP_COMMIT();
    }

    float acc[4][4][4];
    #pragma unroll
    for (int i = 0; i < 4; i++)
        #pragma unroll
        for (int j = 0; j < 4; j++)
            #pragma unroll
            for (int r = 0; r < 4; r++) acc[i][j][r] = 0.f;

    for (int c = 0; c < NC; c++) {
        int buf = c % NSTAGE;
        CP_WAIT1();
        __syncthreads();
        if (c + 2 < NC) {
            uint32_t st = smem_base + ((c + 2) % NSTAGE) * STG_BYTES;
            const bf16* a0 = ag + (c + 2) * BK;
            const bf16* b0 = bg + (c + 2) * BK;
            #pragma unroll
            for (int j = 0; j < 4; j++) cp16(st + sAoff[j], a0 + j * 8);
            #pragma unroll
            for (int j = 0; j < 4; j++) cp16(st + sBoff[j], b0 + j * 8);
        }
        CP_COMMIT();

        uint32_t base = smem_base + buf * STG_BYTES;
        #pragma unroll
        for (int kf = 0; kf < 4; kf++) {
            uint32_t a[4][4], b[2][4];
            #pragma unroll
            for (int mf = 0; mf < 4; mf++)
                ldsm4(a[mf], base + a_rowoff[mf] +
                      (uint32_t)(((((kf << 1) | ahi)) ^ a_rx[mf]) << 4));
            #pragma unroll
            for (int ng = 0; ng < 2; ng++)
                ldsm4(b[ng], base + b_rowoff[ng] +
                      (uint32_t)(((((kf << 1) | bhi)) ^ b_rx[ng]) << 4));
            #pragma unroll
            for (int mf = 0; mf < 4; mf++)
                #pragma unroll
                for (int ng = 0; ng < 2; ng++) {
                    mma_bf16(acc[mf][ng * 2 + 0], a[mf], b[ng][0], b[ng][1]);
                    mma_bf16(acc[mf][ng * 2 + 1], a[mf], b[ng][2], b[ng][3]);
                }
        }
        __syncthreads();
    }

    // epilogue
    int r4 = lane >> 2, c2 = (lane & 3) * 2;
    #pragma unroll
    for (int mf = 0; mf < 4; mf++) {
        int m0 = bm + wm + mf * 16 + r4;
        #pragma unroll
        for (int nf = 0; nf < 4; nf++) {
            int n0 = bn + wn + (nf >> 1) * 16 + (nf & 1) * 8 + c2;
            float bx = 0.f, by = 0.f;
            if (bias) { bx = bias[n0]; by = bias[n0 + 1]; }
            float* ac = acc[mf][nf];
            float x0 = ac[0] * alpha + bx, y0 = ac[1] * alpha + by;
            float x1 = ac[2] * alpha + bx, y1 = ac[3] * alpha + by;
            if (mode == 1) {
                bf16* C = (bf16*)Cv + blockIdx.z * sC;
                bf162 h0 = __floats2bfloat162_rn(x0, y0);
                bf162 h1 = __floats2bfloat162_rn(x1, y1);
                *(bf162*)(C + (size_t)m0 * ldc + n0) = h0;
                *(bf162*)(C + (size_t)(m0 + 8) * ldc + n0) = h1;
            } else if (mode == 0) {
                float* C = (float*)Cv + blockIdx.z * sC;
                *(float2*)(C + (size_t)m0 * ldc + n0) = make_float2(x0, y0);
                *(float2*)(C + (size_t)(m0 + 8) * ldc + n0) = make_float2(x1, y1);
            } else {
                // fused residual + transpose to [B, C, H, W]
                float* C = (float*)Cv;
                int m1 = m0 + 8;
                size_t i00 = (((size_t)(m0 >> 12) * CDIM) + n0) * HWDIM + (m0 & 4095);
                size_t i01 = (((size_t)(m0 >> 12) * CDIM) + n0 + 1) * HWDIM + (m0 & 4095);
                size_t i10 = (((size_t)(m1 >> 12) * CDIM) + n0) * HWDIM + (m1 & 4095);
                size_t i11 = (((size_t)(m1 >> 12) * CDIM) + n0 + 1) * HWDIM + (m1 & 4095);
                C[i00] = x0 + xres[i00];
                C[i01] = y0 + xres[i01];
                C[i10] = x1 + xres[i10];
                C[i11] = y1 + xres[i11];
            }
        }
    }
}

// ---------------- weight f32 -> bf16 (all 4 in one launch) ------------------
__global__ __launch_bounds__(256) void convert_w(const float* __restrict__ W0,
                                                 const float* __restrict__ W1,
                                                 const float* __restrict__ W2,
                                                 const float* __restrict__ W3,
                                                 bf16* __restrict__ out) {
    int i = blockIdx.x * 256 + threadIdx.x;
    const int WN = CDIM * CDIM;
    int sel = i / WN, r = i % WN;
    const float* W = (sel == 0) ? W0 : (sel == 1) ? W1 : (sel == 2) ? W2 : W3;
    out[i] = __float2bfloat16(W[r]);
}

// ---------------- GroupNorm -> bf16 [B,N,C] --------------------------------
__global__ __launch_bounds__(256) void gn_kernel(const float* __restrict__ x,
                                                 const float* __restrict__ gamma,
                                                 const float* __restrict__ beta,
                                                 bf16* __restrict__ xn) {
    int b = blockIdx.x >> 5;
    int g = blockIdx.x & 31;
    const float* xp = x + ((size_t)b * CDIM + (size_t)g * CPG) * HWDIM;
    const int NEL = CPG * HWDIM;

    float s = 0.f, s2 = 0.f;
    for (int i = threadIdx.x; i < NEL; i += 256) {
        float v = xp[i];
        s += v; s2 += v * v;
    }
    __shared__ float rs[256], rs2[256];
    rs[threadIdx.x] = s; rs2[threadIdx.x] = s2;
    __syncthreads();
    for (int st = 128; st > 0; st >>= 1) {
        if (threadIdx.x < st) { rs[threadIdx.x] += rs[threadIdx.x + st];
                                rs2[threadIdx.x] += rs2[threadIdx.x + st]; }
        __syncthreads();
    }
    float mean = rs[0] * (1.f / NEL);
    float var  = rs2[0] * (1.f / NEL) - mean * mean;
    float rstd = rsqrtf(var + EPSV);

    for (int i = threadIdx.x; i < NEL; i += 256) {
        int c  = i & (CPG - 1);
        int hw = i >> 4;
        int cg = g * CPG + c;
        float v = xp[(size_t)c * HWDIM + hw];
        xn[((size_t)b * HWDIM + hw) * CDIM + cg] =
            __float2bfloat16((v - mean) * rstd * gamma[cg] + beta[cg]);
    }
}

// ---------------- Transpose V (bf16): [B,N,C] -> [B,C,N] --------------------
__global__ __launch_bounds__(256) void transpose_vt(const bf16* __restrict__ V,
                                                    bf16* __restrict__ Vt) {
    __shared__ bf16 t[32][34];
    int b  = blockIdx.z;
    int n0 = blockIdx.x * 32;
    int c0 = blockIdx.y * 32;
    int tx = threadIdx.x & 31, ty = threadIdx.x >> 5;
    const size_t str = (size_t)HWDIM * CDIM;
    #pragma unroll
    for (int i = 0; i < 4; i++)
        t[ty + i * 8][tx] = V[b * str + (size_t)(n0 + ty + i * 8) * CDIM + c0 + tx];
    __syncthreads();
    #pragma unroll
    for (int i = 0; i < 4; i++)
        Vt[b * str + (size_t)(c0 + ty + i * 8) * HWDIM + n0 + tx] = t[tx][ty + i * 8];
}

// ---------------- Softmax: f32 S row -> bf16 P row --------------------------
__global__ __launch_bounds__(256) void softmax_kernel(const float* __restrict__ S,
                                                      bf16* __restrict__ P) {
    __shared__ float row[HWDIM];
    __shared__ float red[256];
    const float* g = S + (size_t)blockIdx.x * HWDIM;
    bf16* p = P + (size_t)blockIdx.x * HWDIM;
    int tid = threadIdx.x;

    float m = -1e30f;
    #pragma unroll
    for (int i = 0; i < 4; i++) {
        float4 v = *(const float4*)(g + (tid + i * 256) * 4);
        *(float4*)(row + (tid + i * 256) * 4) = v;
        m = fmaxf(m, fmaxf(fmaxf(v.x, v.y), fmaxf(v.z, v.w)));
    }
    red[tid] = m; __syncthreads();
    for (int st = 128; st > 0; st >>= 1) {
        if (tid < st) red[tid] = fmaxf(red[tid], red[tid + st]);
        __syncthreads();
    }
    m = red[0];
    __syncthreads();

    float sum = 0.f;
    #pragma unroll
    for (int i = 0; i < 4; i++) {
        float4 v = *(float4*)(row + (tid + i * 256) * 4);
        v.x = __expf(v.x - m); v.y = __expf(v.y - m);
        v.z = __expf(v.z - m); v.w = __expf(v.w - m);
        *(float4*)(row + (tid + i * 256) * 4) = v;
        sum += v.x + v.y + v.z + v.w;
    }
    red[tid] = sum; __syncthreads();
    for (int st = 128; st > 0; st >>= 1) {
        if (tid < st) red[tid] += red[tid + st];
        __syncthreads();
    }
    float inv = 1.f / red[0];
    #pragma unroll
    for (int i = 0; i < 4; i++) {
        int i4 = (tid + i * 256) * 4;
        float4 v = *(float4*)(row + i4);
        bf162 h0 = __floats2bfloat162_rn(v.x * inv, v.y * inv);
        bf162 h1 = __floats2bfloat162_rn(v.z * inv, v.w * inv);
        uint2 pk;
        pk.x = *(uint32_t*)&h0;
        pk.y = *(uint32_t*)&h1;
        *(uint2*)(p + i4) = pk;
    }
}

// ---------------- launch ----------------------------------------------------
extern "C" void kernel_launch(void* const* d_in, const int* in_sizes, int n_in,
                              void* d_out, int out_size) {
    const float* x     = (const float*)d_in[0];
    const float* gamma = (const float*)d_in[1];
    const float* beta  = (const float*)d_in[2];
    const float* Wq    = (const float*)d_in[3];
    const float* bq    = (const float*)d_in[4];
    const float* Wk    = (const float*)d_in[5];
    const float* bk    = (const float*)d_in[6];
    const float* Wv    = (const float*)d_in[7];
    const float* bv    = (const float*)d_in[8];
    const float* Wo    = (const float*)d_in[9];
    float* out = (float*)d_out;

    bf16 *xnb, *qb, *kb, *vb, *vtb, *pb, *attnb, *wb;
    float *s;
    cudaGetSymbolAddress((void**)&xnb,   g_xnb);
    cudaGetSymbolAddress((void**)&qb,    g_qb);
    cudaGetSymbolAddress((void**)&kb,    g_kb);
    cudaGetSymbolAddress((void**)&vb,    g_vb);
    cudaGetSymbolAddress((void**)&vtb,   g_vtb);
    cudaGetSymbolAddress((void**)&pb,    g_pb);
    cudaGetSymbolAddress((void**)&attnb, g_attnb);
    cudaGetSymbolAddress((void**)&wb,    g_wb);
    cudaGetSymbolAddress((void**)&s,     g_s);

    static bool attr_set = false;
    if (!attr_set) {
        cudaFuncSetAttribute(gemm_bf16, cudaFuncAttributeMaxDynamicSharedMemorySize, SMEM_DYN);
        attr_set = true;
    }

    const int M_all = BATCH * HWDIM;
    const size_t strQ = (size_t)HWDIM * CDIM;
    const size_t strS = (size_t)HWDIM * HWDIM;
    const int WN = CDIM * CDIM;
    const float inv_sqrt_c = 0.044194173824159216f;

    bf16* wqb = wb;
    bf16* wkb = wb + WN;
    bf16* wvb = wb + 2 * WN;
    bf16* wob = wb + 3 * WN;

    // 0. weights -> bf16 (one launch)
    convert_w<<<4 * WN / 256, 256>>>(Wq, Wk, Wv, Wo, wb);

    // 1. GroupNorm -> bf16 [B,N,C]
    gn_kernel<<<BATCH * 32, 256>>>(x, gamma, beta, xnb);

    // 2. Q/K/V projections (bf16 out)
    dim3 gproj(CDIM / TN, M_all / TM, 1);
    gemm_bf16<<<gproj, 256, SMEM_DYN>>>(xnb, wqb, bq, qb, nullptr,
                                        CDIM, CDIM, CDIM, CDIM, 1.f, 1, 0, 0, 0);
    gemm_bf16<<<gproj, 256, SMEM_DYN>>>(xnb, wkb, bk, kb, nullptr,
                                        CDIM, CDIM, CDIM, CDIM, 1.f, 1, 0, 0, 0);
    gemm_bf16<<<gproj, 256, SMEM_DYN>>>(xnb, wvb, bv, vb, nullptr,
                                        CDIM, CDIM, CDIM, CDIM, 1.f, 1, 0, 0, 0);

    // 3. V^T
    dim3 gtr(HWDIM / 32, CDIM / 32, BATCH);
    transpose_vt<<<gtr, 256>>>(vb, vtb);

    // 4. S = (Q @ K^T) / sqrt(C)  (f32 out)
    dim3 gs(HWDIM / TN, HWDIM / TM, BATCH);
    gemm_bf16<<<gs, 256, SMEM_DYN>>>(qb, kb, nullptr, s, nullptr,
                                     CDIM, CDIM, CDIM, HWDIM,
                                     inv_sqrt_c, 0, strQ, strQ, strS);

    // 5. softmax -> bf16 P
    softmax_kernel<<<M_all, 256>>>(s, pb);

    // 6. A = P @ Vt^T  (bf16 out)
    dim3 gpv(CDIM / TN, HWDIM / TM, BATCH);
    gemm_bf16<<<gpv, 256, SMEM_DYN>>>(pb, vtb, nullptr, attnb, nullptr,
                                      HWDIM, HWDIM, HWDIM, CDIM,
                                      1.f, 1, strS, strQ, strQ);

    // 7. O = A @ Wo^T fused with residual + transpose to [B,C,H,W]
    gemm_bf16<<<gproj, 256, SMEM_DYN>>>(attnb, wob, nullptr, out, x,
                                        CDIM, CDIM, CDIM, CDIM, 1.f, 2, 0, 0, 0);
}